// round 9
// baseline (speedup 1.0000x reference)
#include <cuda_runtime.h>
#include <cuda_fp16.h>
#include <cstdint>

#define B_   128
#define T_   256
#define K_   256
#define NTH  256
#define KF   192            // k-range on HFMA2 pipe; [KF,256) on tensor pipe
#define LOG2E 1.4426950408889634f
#define LN2   0.6931471805599453f

static __device__ __forceinline__ uint32_t packh2(float lo, float hi) {
    __half2 h = __floats2half2_rn(lo, hi);
    return *reinterpret_cast<uint32_t*>(&h);
}
static __device__ __forceinline__ void mma16816(float* d, const uint32_t* a,
                                                uint32_t b0, uint32_t b1) {
    asm volatile(
        "mma.sync.aligned.m16n8k16.row.col.f32.f16.f16.f32 "
        "{%0,%1,%2,%3}, {%4,%5,%6,%7}, {%8,%9}, {%0,%1,%2,%3};"
        : "+f"(d[0]), "+f"(d[1]), "+f"(d[2]), "+f"(d[3])
        : "r"(a[0]), "r"(a[1]), "r"(a[2]), "r"(a[3]), "r"(b0), "r"(b1));
}

__global__ __launch_bounds__(NTH, 1)
void crf_loss_kernel(const float* __restrict__ feats,   // [B,T,K]
                     const float* __restrict__ trans,   // [K,K]
                     const int*   __restrict__ tags,    // [B,T]
                     const int*   __restrict__ lens,    // [B]
                     float*       __restrict__ out)     // [B]
{
    __shared__ __align__(16) __half es[2][K_];   // scaled exp(state), fp16
    __shared__ int   gsh[2];
    __shared__ float red[8];

    const int tid  = threadIdx.x;
    const int lane = tid & 31;
    const int w    = tid >> 5;        // 8 warps; warp w owns to in [32w, 32w+32)
    const int to   = tid;
    const int tg   = lane & 3;
    const int g4   = lane >> 2;
    const int b    = blockIdx.x;

    // ---- HFMA2 operand: ET2[c] = (exp tr[2c][to], exp tr[2c+1][to]), k < KF ----
    uint32_t ET2[KF / 2];
    {
        const float* tp = trans + to;
        #pragma unroll
        for (int c = 0; c < KF / 2; ++c) {
            float e0 = __expf(__ldg(tp + (size_t)(2 * c)     * K_));
            float e1 = __expf(__ldg(tp + (size_t)(2 * c + 1) * K_));
            ET2[c] = packh2(e0, e1);
        }
    }
    // ---- HMMA A-frags for k in [KF,256): tiles m=0,1 cover rows 32w+16m.. ----
    uint32_t AH[2][4][4];
    #pragma unroll
    for (int m = 0; m < 2; ++m) {
        const int r = 32 * w + 16 * m + g4;
        #pragma unroll
        for (int kt = 0; kt < 4; ++kt) {
            const int k0 = KF + 16 * kt + 2 * tg;
            AH[m][kt][0] = packh2(__expf(__ldg(trans + (size_t)k0 * K_ + r)),
                                  __expf(__ldg(trans + (size_t)(k0 + 1) * K_ + r)));
            AH[m][kt][1] = packh2(__expf(__ldg(trans + (size_t)k0 * K_ + r + 8)),
                                  __expf(__ldg(trans + (size_t)(k0 + 1) * K_ + r + 8)));
            AH[m][kt][2] = packh2(__expf(__ldg(trans + (size_t)(k0 + 8) * K_ + r)),
                                  __expf(__ldg(trans + (size_t)(k0 + 9) * K_ + r)));
            AH[m][kt][3] = packh2(__expf(__ldg(trans + (size_t)(k0 + 8) * K_ + r + 8)),
                                  __expf(__ldg(trans + (size_t)(k0 + 9) * K_ + r + 8)));
        }
    }

    const int len = lens[b];
    const float* fb = feats + (size_t)b * T_ * K_;

    // ---- init ----
    float f0 = fb[to];
    if (tid == 0) gsh[0] = __float2int_rd(f0 * LOG2E) + 14;
    __syncthreads();
    int   g0 = gsh[0];
    int   C  = g0;
    float v  = exp2f(f0 * LOG2E - (float)g0);
    es[0][to] = __float2half_rn(v);
    float fcur = (len > 1) ? fb[K_ + to] : 0.f;
    __syncthreads();

    // merge constants: my row within warp block = lane
    const int mtile = lane >> 4;          // which m16 tile holds my row
    const int rr    = lane & 15;          // row within tile
    const int srcl  = 4 * (rr & 7);       // lane holding that row (tg=0)
    const bool hi8  = (rr & 8) != 0;      // c2 vs c0

    // ---- forward recurrence: one barrier per step ----
    for (int t = 1; t < len; ++t) {
        const int p = (t - 1) & 1;
        const int q = t & 1;

        const int gp = gsh[p];
        float efv = exp2f(fcur * LOG2E - (float)gp);   // MUFU, hidden under matvec
        C += gp;
        const int tn = (t + 1 < len) ? (t + 1) : t;
        float fnext = fb[(size_t)tn * K_ + to];

        // --- tensor half: k in [KF,256), all n-columns fed identical es ---
        float ah0[4] = {0.f, 0.f, 0.f, 0.f};
        float ah1[4] = {0.f, 0.f, 0.f, 0.f};
        {
            const __half* eh = &es[p][KF];
            #pragma unroll
            for (int kt = 0; kt < 4; ++kt) {
                uint32_t b0 = *reinterpret_cast<const uint32_t*>(eh + 16 * kt + 2 * tg);
                uint32_t b1 = *reinterpret_cast<const uint32_t*>(eh + 16 * kt + 2 * tg + 8);
                mma16816(ah0, AH[0][kt], b0, b1);
                mma16816(ah1, AH[1][kt], b0, b1);
            }
        }

        // --- fma half: k in [0,KF), 4 fp16x2 chains ---
        __half2 zz = __float2half2_rn(0.f);
        __half2 a0 = zz, a1 = zz, a2 = zz, a3 = zz;
        const uint4* ep = reinterpret_cast<const uint4*>(es[p]);
        #pragma unroll
        for (int i = 0; i < KF / 8; ++i) {
            uint4 qv = ep[i];   // warp-uniform broadcast
            a0 = __hfma2(*reinterpret_cast<__half2*>(&ET2[4 * i + 0]),
                         *reinterpret_cast<__half2*>(&qv.x), a0);
            a1 = __hfma2(*reinterpret_cast<__half2*>(&ET2[4 * i + 1]),
                         *reinterpret_cast<__half2*>(&qv.y), a1);
            a2 = __hfma2(*reinterpret_cast<__half2*>(&ET2[4 * i + 2]),
                         *reinterpret_cast<__half2*>(&qv.z), a2);
            a3 = __hfma2(*reinterpret_cast<__half2*>(&ET2[4 * i + 3]),
                         *reinterpret_cast<__half2*>(&qv.w), a3);
        }
        a0 = __hadd2(a0, a1);
        a2 = __hadd2(a2, a3);
        a0 = __hadd2(a0, a2);
        float2 fx = __half22float2(a0);
        float s_lo = fx.x + fx.y;

        // --- merge tensor result to owner thread (row = lane) ---
        float x00 = __shfl_sync(0xffffffffu, ah0[0], srcl);
        float x02 = __shfl_sync(0xffffffffu, ah0[2], srcl);
        float x10 = __shfl_sync(0xffffffffu, ah1[0], srcl);
        float x12 = __shfl_sync(0xffffffffu, ah1[2], srcl);
        float v0m = hi8 ? x02 : x00;
        float v1m = hi8 ? x12 : x10;
        float d_hi = mtile ? v1m : v0m;

        v = (s_lo + d_hi) * efv;
        es[q][to] = __float2half_rn(v);
        if (tid == 0)
            gsh[q] = ((__float_as_int(v) >> 23) & 255) - 113;
        fcur = fnext;
        __syncthreads();
    }

    // ---- forward_score = logsumexp_{to}(state) ----
    float state = (log2f(v) + (float)C) * LN2;

    float x = state;
    #pragma unroll
    for (int o = 16; o > 0; o >>= 1)
        x = fmaxf(x, __shfl_xor_sync(0xffffffffu, x, o));
    if (lane == 0) red[w] = x;
    __syncthreads();
    float bm = red[0];
    #pragma unroll
    for (int i = 1; i < 8; ++i) bm = fmaxf(bm, red[i]);
    __syncthreads();

    float e = __expf(state - bm);
    #pragma unroll
    for (int o = 16; o > 0; o >>= 1)
        e += __shfl_xor_sync(0xffffffffu, e, o);
    if (lane == 0) red[w] = e;
    __syncthreads();
    float ssum = red[0];
    #pragma unroll
    for (int i = 1; i < 8; ++i) ssum += red[i];
    float forward = bm + __logf(ssum);
    __syncthreads();

    // ---- gold path score: thread tid handles timestep tid ----
    float u = 0.f;
    if (tid < len) {
        int tg2a = tags[b * T_ + tid];
        u = fb[(size_t)tid * K_ + tg2a];
        if (tid + 1 < len) {
            int tg2b = tags[b * T_ + tid + 1];
            u += __ldg(trans + (size_t)tg2a * K_ + tg2b);
        }
    }
    #pragma unroll
    for (int o = 16; o > 0; o >>= 1)
        u += __shfl_xor_sync(0xffffffffu, u, o);
    if (lane == 0) red[w] = u;
    __syncthreads();
    if (tid == 0) {
        float us = red[0];
        #pragma unroll
        for (int i = 1; i < 8; ++i) us += red[i];
        out[b] = forward - us;
    }
}

extern "C" void kernel_launch(void* const* d_in, const int* in_sizes, int n_in,
                              void* d_out, int out_size) {
    const float* feats = (const float*)d_in[0];
    const float* trans = (const float*)d_in[1];
    const int*   tags  = (const int*)d_in[2];
    const int*   lens  = (const int*)d_in[3];
    float*       out   = (float*)d_out;

    crf_loss_kernel<<<B_, NTH>>>(feats, trans, tags, lens, out);
}

// round 10
// speedup vs baseline: 1.0164x; 1.0164x over previous
#include <cuda_runtime.h>
#include <cuda_fp16.h>
#include <cstdint>

#define B_   128
#define T_   256
#define K_   256
#define NTH  256
#define LOG2E 1.4426950408889634f
#define LN2   0.6931471805599453f

static __device__ __forceinline__ uint32_t packh2(float lo, float hi) {
    __half2 h = __floats2half2_rn(lo, hi);
    return *reinterpret_cast<uint32_t*>(&h);
}
static __device__ __forceinline__ float ex2f(float x) {   // raw MUFU, no library
    float r;
    asm("ex2.approx.f32 %0, %1;" : "=f"(r) : "f"(x));
    return r;
}
static __device__ __forceinline__ void bar_arrive(int id) {
    asm volatile("bar.arrive %0, %1;" :: "r"(id), "r"(2 * NTH) : "memory");
}
static __device__ __forceinline__ void bar_wait(int id) {
    asm volatile("bar.sync %0, %1;" :: "r"(id), "r"(2 * NTH) : "memory");
}

__global__ __launch_bounds__(NTH, 1)
void crf_loss_kernel(const float* __restrict__ feats,   // [B,T,K]
                     const float* __restrict__ trans,   // [K,K]
                     const int*   __restrict__ tags,    // [B,T]
                     const int*   __restrict__ lens,    // [B]
                     float*       __restrict__ out)     // [B]
{
    __shared__ __align__(16) __half es[2][K_];   // scaled exp(state), fp16
    __shared__ int   gsh[2];
    __shared__ float red[8];

    const int tid  = threadIdx.x;
    const int lane = tid & 31;
    const int w    = tid >> 5;        // 8 warps
    const int to   = tid;             // one full "to" column per thread
    const int b    = blockIdx.x;

    // ---- ET in registers: ET2[c] = (exp tr[2c][to], exp tr[2c+1][to]) ----
    uint32_t ET2[128];
    {
        const float* tp = trans + to;
        #pragma unroll
        for (int c = 0; c < 128; ++c) {
            float e0 = __expf(__ldg(tp + (size_t)(2 * c)     * K_));
            float e1 = __expf(__ldg(tp + (size_t)(2 * c + 1) * K_));
            ET2[c] = packh2(e0, e1);
        }
    }

    const int len = lens[b];
    const float* fb = feats + (size_t)b * T_ * K_;

    // ---- init: v0 = ex2(f0*log2e - g0), C = g0 ----
    float f0 = fb[to];
    if (tid == 0) gsh[0] = __float2int_rd(f0 * LOG2E) + 14;
    __syncthreads();                                   // HW barrier 0 (balanced)
    int   g0 = gsh[0];
    int   C  = g0;
    float v  = ex2f(f0 * LOG2E - (float)g0);
    es[0][to] = __float2half_rn(v);
    bar_arrive(1);                                     // es[0] + gsh[0] published
    float fl2 = ((len > 1) ? fb[K_ + to] : 0.f) * LOG2E;   // f_1 * log2e

    // ---- forward recurrence: split-barrier pipeline, ids 1 (buf0) / 2 (buf1) ----
    for (int t = 1; t < len; ++t) {
        const int p = (t - 1) & 1;
        const int q = t & 1;

        bar_wait(1 + p);                               // es[p], gsh[p] ready

        const int gp = gsh[p];
        float efv = ex2f(fl2 - (float)gp);             // 1 MUFU, hidden under matvec
        C += gp;
        const int tn = (t + 1 < len) ? (t + 1) : t;
        float fl2n = fb[(size_t)tn * K_ + to] * LOG2E; // prefetch f_{t+1}

        // full matvec for my column: 256 from-values, 8 fp16x2 chains (depth 16)
        __half2 zz = __float2half2_rn(0.f);
        __half2 a[8] = {zz, zz, zz, zz, zz, zz, zz, zz};
        const uint4* ep = reinterpret_cast<const uint4*>(es[p]);
        #pragma unroll
        for (int i = 0; i < 32; ++i) {
            uint4 qv = ep[i];                          // warp-uniform broadcast
            const int o = (i & 1) * 4;
            a[o + 0] = __hfma2(*reinterpret_cast<__half2*>(&ET2[4 * i + 0]),
                               *reinterpret_cast<__half2*>(&qv.x), a[o + 0]);
            a[o + 1] = __hfma2(*reinterpret_cast<__half2*>(&ET2[4 * i + 1]),
                               *reinterpret_cast<__half2*>(&qv.y), a[o + 1]);
            a[o + 2] = __hfma2(*reinterpret_cast<__half2*>(&ET2[4 * i + 2]),
                               *reinterpret_cast<__half2*>(&qv.z), a[o + 2]);
            a[o + 3] = __hfma2(*reinterpret_cast<__half2*>(&ET2[4 * i + 3]),
                               *reinterpret_cast<__half2*>(&qv.w), a[o + 3]);
        }
        __half2 c0 = __hadd2(a[0], a[4]);
        __half2 c1 = __hadd2(a[1], a[5]);
        __half2 c2 = __hadd2(a[2], a[6]);
        __half2 c3 = __hadd2(a[3], a[7]);
        c0 = __hadd2(c0, c1);
        c2 = __hadd2(c2, c3);
        c0 = __hadd2(c0, c2);
        float2 fx = __half22float2(c0);
        float s = fx.x + fx.y;

        v = s * efv;                                   // fp32 (subnormal-safe exponent)
        es[q][to] = __float2half_rn(v);
        if (tid == 0)
            gsh[q] = ((__float_as_int(v) >> 23) & 255) - 113;
        bar_arrive(1 + q);                             // publish es[q], gsh[q]
        fl2 = fl2n;
    }

    // ---- forward_score = logsumexp_{to}(state) ----
    float state = (log2f(v) + (float)C) * LN2;

    float x = state;
    #pragma unroll
    for (int o = 16; o > 0; o >>= 1)
        x = fmaxf(x, __shfl_xor_sync(0xffffffffu, x, o));
    if (lane == 0) red[w] = x;
    __syncthreads();
    float bm = red[0];
    #pragma unroll
    for (int i = 1; i < 8; ++i) bm = fmaxf(bm, red[i]);
    __syncthreads();

    float e = __expf(state - bm);
    #pragma unroll
    for (int o = 16; o > 0; o >>= 1)
        e += __shfl_xor_sync(0xffffffffu, e, o);
    if (lane == 0) red[w] = e;
    __syncthreads();
    float ssum = red[0];
    #pragma unroll
    for (int i = 1; i < 8; ++i) ssum += red[i];
    float forward = bm + __logf(ssum);
    __syncthreads();

    // ---- gold path score: thread tid handles timestep tid (T_ == NTH) ----
    float u = 0.f;
    if (tid < len) {
        int tg = tags[b * T_ + tid];
        u = fb[(size_t)tid * K_ + tg];
        if (tid + 1 < len) {
            int tg2 = tags[b * T_ + tid + 1];
            u += __ldg(trans + (size_t)tg * K_ + tg2);
        }
    }
    #pragma unroll
    for (int o = 16; o > 0; o >>= 1)
        u += __shfl_xor_sync(0xffffffffu, u, o);
    if (lane == 0) red[w] = u;
    __syncthreads();
    if (tid == 0) {
        float us = red[0];
        #pragma unroll
        for (int i = 1; i < 8; ++i) us += red[i];
        out[b] = forward - us;
    }
}

extern "C" void kernel_launch(void* const* d_in, const int* in_sizes, int n_in,
                              void* d_out, int out_size) {
    const float* feats = (const float*)d_in[0];
    const float* trans = (const float*)d_in[1];
    const int*   tags  = (const int*)d_in[2];
    const int*   lens  = (const int*)d_in[3];
    float*       out   = (float*)d_out;

    crf_loss_kernel<<<B_, NTH>>>(feats, trans, tags, lens, out);
}